// round 15
// baseline (speedup 1.0000x reference)
#include <cuda_runtime.h>
#include <cstdint>

// Problem constants (fixed for this problem instance)
#define RR 20000   // reviews
#define SS 64      // words per review
#define DD 128     // embedding dim
#define KK 32      // aspects
#define BB 2048    // batch
#define LL 20480   // history length (both user and item)
#define PER (LL / BB)   // 10: exact entries per segment (seg = arange(L)//(L/B))

#define GRID_REVIEW 592   // 4 blocks/SM x 148 SMs

// ---------------- device scratch (no allocation allowed) ----------------
__device__ float g_mwT[DD * DD];  // M_w transposed: g_mwT[e*DD+d] = M_w[d*DD+e]
__device__ float g_rs[RR * DD];   // per-review aspect embedding r_s

// ================= kernel 0: transpose M_w (one-shot, ~3us) =================
__global__ void mwprep_kernel(const float* __restrict__ Mw) {
    int i = blockIdx.x * 256 + threadIdx.x;   // 64 blocks x 256 = 16384
    int d = i >> 7, e = i & 127;
    g_mwT[e * DD + d] = Mw[i];                // coalesced read, scattered write (tiny)
}

// ================= kernel 1: persistent fused review pipeline =================
// v = M_w @ y is computed INLINE per iteration (vprep kernel eliminated):
// warp w owns e-range [w*16, w*16+16), lane owns d = 4*lane..4*lane+3 ->
// 16 independent LDG.128 of L1-resident g_mwT + 64 FFMA per thread, then the
// same cross-warp reduce pattern as the z phase. y (512B) is prefetched one
// iteration ahead exactly as g_v used to be; next review's wemb gathers are
// still issued right after the z-partial frees ev[].
__global__ void __launch_bounds__(256, 4) review_kernel(
    const int*   __restrict__ tok,    // [R,S]
    const float* __restrict__ ypos,   // [R,D]
    const float* __restrict__ wemb,   // [V,D]
    const float* __restrict__ Ww,     // [D,K]
    const float* __restrict__ Wb,     // [K]
    const float* __restrict__ Tw,     // [K,D]
    const float* __restrict__ Tb)     // [D]
{
    __shared__ float wwS[KK * 129];   // [k][d], stride 129 -> bank (k+d)%32
    __shared__ float twS[KK * DD];    // [k][d]
    __shared__ float wb_sh[KK];
    __shared__ float y_sh[DD];
    __shared__ float v_sh[DD];
    __shared__ float ax_sh[SS];
    __shared__ float red[8 * DD];     // per-warp partials (v phase AND z phase)
    __shared__ float z_sh[DD];
    __shared__ float lpart[8 * KK];
    __shared__ float p_sh[KK];

    const int t    = threadIdx.x;
    const int lane = t & 31;
    const int w    = t >> 5;

    // ---- one-time per-block staging ----
    for (int i = t; i < DD * KK; i += 256) {
        int d = i >> 5, k = i & 31;
        wwS[k * 129 + d] = Ww[i];
        twS[i] = Tw[i];
    }
    if (t < KK) wb_sh[t] = Wb[t];
    const float tb_reg = (t < DD) ? Tb[t] : 0.f;
    const int   part   = t >> 5;
    const float* wwrow = wwS + lane * 129 + part * 16;   // lane = logit k

    // v-compute pointers: warp w -> e in [w*16, w*16+16), lane -> d4 chunk
    const float4* mwT4 = reinterpret_cast<const float4*>(g_mwT);

    // ---- prologue: first review's tokens (per-warp regs), y, and gathers ----
    const int rfirst = blockIdx.x;
    int tokreg = 0;
    if (lane < 8) tokreg = __ldg(tok + rfirst * SS + w * 8 + lane);
    float y_pf = (t < DD) ? ypos[(size_t)rfirst * DD + t] : 0.f;

    float4 ev[8];
    #pragma unroll
    for (int i = 0; i < 8; ++i) {
        int id = __shfl_sync(0xffffffffu, tokreg, i);
        ev[i] = reinterpret_cast<const float4*>(wemb + (size_t)id * DD)[lane];
    }
    if (t < DD) y_sh[t] = y_pf;
    __syncthreads();

    for (int r = rfirst; r < RR; r += GRID_REVIEW) {
        const int rn = r + GRID_REVIEW;
        const int rc = (rn < RR) ? rn : r;

        // ---- inline v: warp-partial GEMV on L1-resident mwT ----
        {
            float4 a4 = make_float4(0.f, 0.f, 0.f, 0.f);
            const int e0 = w * 16;
            #pragma unroll
            for (int e = 0; e < 16; ++e) {
                float4 m = mwT4[(size_t)(e0 + e) * (DD / 4) + lane];  // L1-hot LDG.128
                float  y = y_sh[e0 + e];                              // broadcast LDS
                a4.x = fmaf(m.x, y, a4.x);
                a4.y = fmaf(m.y, y, a4.y);
                a4.z = fmaf(m.z, y, a4.z);
                a4.w = fmaf(m.w, y, a4.w);
            }
            reinterpret_cast<float4*>(red)[w * 32 + lane] = a4;
        }
        __syncthreads();                                   // Bv1
        if (t < DD) {
            float s = 0.f;
            #pragma unroll
            for (int w2 = 0; w2 < 8; ++w2)
                s += red[w2 * DD + t];
            v_sh[t] = s;
        }
        __syncthreads();                                   // Bv2

        const float4 v4 = reinterpret_cast<float4*>(v_sh)[lane];

        // ---- per-lane partial dots for this warp's 8 s-values ----
        float p[8];
        #pragma unroll
        for (int i = 0; i < 8; ++i)
            p[i] = ev[i].x * v4.x + ev[i].y * v4.y +
                   ev[i].z * v4.z + ev[i].w * v4.w;

        // ---- prefetch next review's tokens + y (regs; consumed in tail) ----
        int tokreg_n = 0;
        if (lane < 8) tokreg_n = __ldg(tok + rc * SS + w * 8 + lane);
        float y_pf_n = (t < DD) ? ypos[(size_t)rc * DD + t] : 0.f;

        // ---- folding multi-reduce: 8 dots -> 9 shfls ----
        float q[4];
        #pragma unroll
        for (int i = 0; i < 4; ++i) {
            float send = (lane & 16) ? p[i] : p[i + 4];
            float keep = (lane & 16) ? p[i + 4] : p[i];
            q[i] = keep + __shfl_xor_sync(0xffffffffu, send, 16);
        }
        float u[2];
        #pragma unroll
        for (int i = 0; i < 2; ++i) {
            float send = (lane & 8) ? q[i] : q[i + 2];
            float keep = (lane & 8) ? q[i + 2] : q[i];
            u[i] = keep + __shfl_xor_sync(0xffffffffu, send, 8);
        }
        float dx;
        {
            float send = (lane & 4) ? u[0] : u[1];
            float keep = (lane & 4) ? u[1] : u[0];
            dx = keep + __shfl_xor_sync(0xffffffffu, send, 4);
        }
        dx += __shfl_xor_sync(0xffffffffu, dx, 2);
        dx += __shfl_xor_sync(0xffffffffu, dx, 1);
        if ((lane & 3) == 0) ax_sh[w * 8 + ((lane >> 2) & 7)] = dx;
        __syncthreads();                                   // B1

        // ---- softmax over S=64 (redundant in every warp) + z partial ----
        float4 z = make_float4(0.f, 0.f, 0.f, 0.f);
        {
            float a = ax_sh[lane];
            float b = ax_sh[lane + 32];
            float m = fmaxf(a, b);
            #pragma unroll
            for (int o = 16; o; o >>= 1) m = fmaxf(m, __shfl_xor_sync(0xffffffffu, m, o));
            float ea = __expf(a - m), eb = __expf(b - m);
            float s = ea + eb;
            #pragma unroll
            for (int o = 16; o; o >>= 1) s += __shfl_xor_sync(0xffffffffu, s, o);
            float inv = __fdividef(1.f, s);
            float sel  = (w & 4) ? eb : ea;
            int   base = (w & 3) * 8;
            #pragma unroll
            for (int i = 0; i < 8; ++i) {
                float av = __shfl_sync(0xffffffffu, sel, base + i) * inv;
                z.x = fmaf(av, ev[i].x, z.x);
                z.y = fmaf(av, ev[i].y, z.y);
                z.z = fmaf(av, ev[i].z, z.z);
                z.w = fmaf(av, ev[i].w, z.w);
            }
        }

        // ---- ev[] now dead: ISSUE NEXT REVIEW'S GATHERS (latency hides
        //      under the whole aspect tail below) ----
        #pragma unroll
        for (int i = 0; i < 8; ++i) {
            int id = __shfl_sync(0xffffffffu, tokreg_n, i);
            ev[i] = reinterpret_cast<const float4*>(wemb + (size_t)id * DD)[lane];
        }

        reinterpret_cast<float4*>(red)[w * 32 + lane] = z;
        __syncthreads();                                   // B2

        // ---- z[d]: cross-warp sum of 8 partials ----
        if (t < DD) {
            float s = 0.f;
            #pragma unroll
            for (int w2 = 0; w2 < 8; ++w2)
                s += red[w2 * DD + t];
            z_sh[t] = s;
        }
        __syncthreads();                                   // B3

        // ---- aspect logits: thread (part, lane=k) -> 16-d partial ----
        {
            float a = 0.f;
            const float* zp = z_sh + part * 16;
            #pragma unroll
            for (int j = 0; j < 16; ++j)
                a = fmaf(zp[j], wwrow[j], a);
            lpart[part * KK + lane] = a;
        }
        __syncthreads();                                   // B4

        // ---- K-softmax: warp 0 only -> p_sh ----
        if (w == 0) {
            float a = wb_sh[lane];
            #pragma unroll
            for (int pp = 0; pp < 8; ++pp) a += lpart[pp * KK + lane];
            float m = a;
            #pragma unroll
            for (int o = 16; o; o >>= 1) m = fmaxf(m, __shfl_xor_sync(0xffffffffu, m, o));
            float e = __expf(a - m);
            float s = e;
            #pragma unroll
            for (int o = 16; o; o >>= 1) s += __shfl_xor_sync(0xffffffffu, s, o);
            p_sh[lane] = e * __fdividef(1.f, s);
        }
        __syncthreads();                                   // B5

        // ---- r_s[d] = Tb[d] + sum_k p[k] * Tw[k][d] (p via LDS broadcast) ----
        if (t < DD) {
            float a = tb_reg;
            #pragma unroll
            for (int k = 0; k < KK; ++k)
                a = fmaf(p_sh[k], twS[k * DD + t], a);
            g_rs[(size_t)r * DD + t] = a;
        }

        // ---- stage next y into SMEM; rotate token regs ----
        if (t < DD) y_sh[t] = y_pf_n;
        tokreg = tokreg_n;
        __syncthreads();   // B6: protects y_sh/ax_sh/red/lpart/p_sh for next iter
    }
}

// ================= kernel 2: fused segment-mean + prediction =================
__global__ void __launch_bounds__(256) final_kernel(
    const int*   __restrict__ user, const int* __restrict__ item,
    const int*   __restrict__ uidx, const int* __restrict__ iidx,
    const float* __restrict__ uemb, const float* __restrict__ iemb,
    const float* __restrict__ avg,  float* __restrict__ out)
{
    __shared__ float sh[256];
    __shared__ float red[4];

    const int b    = blockIdx.x;
    const int t    = threadIdx.x;
    const int side = t >> 7;          // 0 = user, 1 = item
    const int d    = t & 127;

    float uf = 0.f, itf = 0.f;
    if (t < DD) {
        uf  = uemb[(size_t)user[b] * DD + t];
        itf = iemb[(size_t)item[b] * DD + t];
    }

    const int* idxp = side ? iidx : uidx;
    const int  base = b * PER;

    int ids[PER];
    #pragma unroll
    for (int j = 0; j < PER; ++j)
        ids[j] = __ldg(idxp + base + j);      // PER independent LDG

    float sum = 0.f;
    #pragma unroll
    for (int j = 0; j < PER; ++j)
        sum += g_rs[(size_t)ids[j] * DD + d]; // PER independent LDG

    sh[t] = sum * (1.0f / (float)PER);
    __syncthreads();

    if (t < DD) {
        float p = sh[t] * sh[t + 128] + uf * itf;
        #pragma unroll
        for (int o = 16; o; o >>= 1) p += __shfl_xor_sync(0xffffffffu, p, o);
        if ((t & 31) == 0) red[t >> 5] = p;
    }
    __syncthreads();
    if (t == 0) out[b] = red[0] + red[1] + red[2] + red[3] + avg[0];
}

// ---------------- launch ----------------
extern "C" void kernel_launch(void* const* d_in, const int* in_sizes, int n_in,
                              void* d_out, int out_size)
{
    const int*   user = (const int*)  d_in[0];
    const int*   item = (const int*)  d_in[1];
    const int*   hrev = (const int*)  d_in[2];
    const float* ypos = (const float*)d_in[3];
    const int*   uidx = (const int*)  d_in[4];
    const int*   iidx = (const int*)  d_in[6];
    const float* wemb = (const float*)d_in[8];
    const float* Mw   = (const float*)d_in[9];
    // d_in[10] = M_b: constant shift over s -> cancels in softmax, unused
    const float* Ww   = (const float*)d_in[11];
    const float* Wb   = (const float*)d_in[12];
    const float* Tw   = (const float*)d_in[13];
    const float* Tb   = (const float*)d_in[14];
    const float* uemb = (const float*)d_in[15];
    const float* iemb = (const float*)d_in[16];
    const float* avg  = (const float*)d_in[17];
    float* out = (float*)d_out;

    mwprep_kernel<<<DD * DD / 256, 256>>>(Mw);          // one-shot transpose
    review_kernel<<<GRID_REVIEW, 256>>>(hrev, ypos, wemb, Ww, Wb, Tw, Tb);
    final_kernel <<<BB, 256>>>(user, item, uidx, iidx, uemb, iemb, avg, out);
}

// round 16
// speedup vs baseline: 1.1690x; 1.1690x over previous
#include <cuda_runtime.h>
#include <cstdint>

// Problem constants (fixed for this problem instance)
#define RR 20000   // reviews
#define SS 64      // words per review
#define DD 128     // embedding dim
#define KK 32      // aspects
#define BB 2048    // batch
#define LL 20480   // history length (both user and item)
#define PER (LL / BB)   // 10: exact entries per segment (seg = arange(L)//(L/B))

#define GRID_REVIEW 592   // 4 blocks/SM x 148 SMs

// ---------------- device scratch (no allocation allowed) ----------------
__device__ float g_v[RR * DD];    // v[r] = M_w @ y[r]
__device__ float g_rs[RR * DD];   // per-review aspect embedding r_s

// ---- packed fp32x2 helpers (FFMA2: 2x fp32 issue rate on sm_103a) ----
#define FMA2(acc, a, b) \
    asm("fma.rn.f32x2 %0, %1, %2, %0;" : "+l"(acc) : "l"(a), "l"(b))
#define PACK2(dst, xu) \
    asm("mov.b64 %0, {%1, %1};" : "=l"(dst) : "r"(xu))
#define UNPACK2(lo, hi, src) \
    asm("mov.b64 {%0, %1}, %2;" : "=r"(lo), "=r"(hi) : "l"(src))

// ================= kernel 1: v[r,d] = sum_e M_w[d,e] * y[r,e] =================
// R13 configuration (verbatim — measured 34.0us, best of 6 variants):
// 625 blocks x 32 reviews x 128 thr, single wave, half-warp-broadcast LDS
// (each LDS.128 feeds 8 reviews = 2 MAC/byte of crossbar).
__global__ void __launch_bounds__(128, 6) vprep_kernel(
    const float* __restrict__ Mw,    // [D,D] row-major: Mw[d*DD+e]
    const float* __restrict__ ypos)  // [R,D]
{
    __shared__ float mw_sh[64 * 132];   // [e_local][d], padded row stride 132

    const int t  = threadIdx.x;          // 0..127
    const int dg = t & 15;               // d chunk: d = 4*dg + 64*j
    const int rg = t >> 4;               // 0..7 -> 4 reviews each
    const int rbase = blockIdx.x * 32 + rg * 4;   // 625*32 = 20000 exact
    const float* yb = ypos + (size_t)rbase * DD;

    unsigned long long acc[4][2][2];   // [review][j][half]
    #pragma unroll
    for (int rv = 0; rv < 4; ++rv)
        #pragma unroll
        for (int j = 0; j < 2; ++j) { acc[rv][j][0] = 0ull; acc[rv][j][1] = 0ull; }

    for (int h = 0; h < 2; ++h) {           // two 64-e halves of M_w
        __syncthreads();
        for (int i = t; i < 128 * 64; i += 128) {
            int d = i >> 6, el = i & 63;                     // coalesced LDG
            mw_sh[el * 132 + d] = Mw[d * DD + h * 64 + el];
        }
        __syncthreads();

        #pragma unroll 4
        for (int e2 = 0; e2 < 32; ++e2) {
            float2 ya[4];
            #pragma unroll
            for (int rv = 0; rv < 4; ++rv)
                ya[rv] = *reinterpret_cast<const float2*>(
                             yb + rv * DD + h * 64 + e2 * 2);   // broadcast LDG.64

            #pragma unroll
            for (int j2 = 0; j2 < 2; ++j2) {
                const int e = e2 * 2 + j2;
                const ulonglong2* mrow =
                    reinterpret_cast<const ulonglong2*>(mw_sh + e * 132);
                const ulonglong2 m0 = mrow[dg];        // half-warp broadcast
                const ulonglong2 m1 = mrow[dg + 16];
                #pragma unroll
                for (int rv = 0; rv < 4; ++rv) {
                    unsigned long long pr;
                    PACK2(pr, __float_as_uint(j2 ? ya[rv].y : ya[rv].x));
                    FMA2(acc[rv][0][0], m0.x, pr);
                    FMA2(acc[rv][0][1], m0.y, pr);
                    FMA2(acc[rv][1][0], m1.x, pr);
                    FMA2(acc[rv][1][1], m1.y, pr);
                }
            }
        }
    }

    #pragma unroll
    for (int rv = 0; rv < 4; ++rv) {
        float* vrow = g_v + (size_t)(rbase + rv) * DD;
        #pragma unroll
        for (int j = 0; j < 2; ++j) {
            unsigned v0, v1, v2, v3;
            UNPACK2(v0, v1, acc[rv][j][0]);
            UNPACK2(v2, v3, acc[rv][j][1]);
            float4 o = make_float4(__uint_as_float(v0), __uint_as_float(v1),
                                   __uint_as_float(v2), __uint_as_float(v3));
            *reinterpret_cast<float4*>(vrow + 4 * dg + 64 * j) = o;
        }
    }
}

// ================= kernel 2: persistent fused review pipeline =================
// R13 structure + vectorized aspect tail: wwS padded to stride 132 (16B
// aligned, chunk 33k%8=k%8 -> conflict-free LDS.128); logit phase reads
// z_sh + wwrow as float4 (32->8 instr, z-broadcast 16->4 wf/warp); rs phase
// reads p_sh as float4 (32->8 broadcast wf/warp). Math order unchanged.
__global__ void __launch_bounds__(256, 4) review_kernel(
    const int*   __restrict__ tok,    // [R,S]
    const float* __restrict__ wemb,   // [V,D]
    const float* __restrict__ Ww,     // [D,K]
    const float* __restrict__ Wb,     // [K]
    const float* __restrict__ Tw,     // [K,D]
    const float* __restrict__ Tb)     // [D]
{
    __shared__ __align__(16) float wwS[KK * 132];   // [k][d], stride 132
    __shared__ __align__(16) float twS[KK * DD];    // [k][d]
    __shared__ __align__(16) float wb_sh[KK];
    __shared__ __align__(16) float v_sh[DD];
    __shared__ __align__(16) float ax_sh[SS];
    __shared__ __align__(16) float red[8 * DD];     // per-warp z partials
    __shared__ __align__(16) float z_sh[DD];
    __shared__ __align__(16) float lpart[8 * KK];
    __shared__ __align__(16) float p_sh[KK];

    const int t    = threadIdx.x;
    const int lane = t & 31;
    const int w    = t >> 5;

    // ---- one-time per-block staging ----
    for (int i = t; i < DD * KK; i += 256) {
        int d = i >> 5, k = i & 31;
        wwS[k * 132 + d] = Ww[i];
        twS[i] = Tw[i];
    }
    if (t < KK) wb_sh[t] = Wb[t];
    const float tb_reg = (t < DD) ? Tb[t] : 0.f;
    const int   part   = t >> 5;
    const float4* wwrow4 =
        reinterpret_cast<const float4*>(wwS + lane * 132 + part * 16);

    // ---- prologue: first review's tokens (per-warp regs), v, and gathers ----
    const int rfirst = blockIdx.x;
    int tokreg = 0;
    if (lane < 8) tokreg = __ldg(tok + rfirst * SS + w * 8 + lane);
    float v_pf = (t < DD) ? g_v[(size_t)rfirst * DD + t] : 0.f;

    float4 ev[8];
    #pragma unroll
    for (int i = 0; i < 8; ++i) {
        int id = __shfl_sync(0xffffffffu, tokreg, i);
        ev[i] = reinterpret_cast<const float4*>(wemb + (size_t)id * DD)[lane];
    }
    if (t < DD) v_sh[t] = v_pf;
    __syncthreads();

    for (int r = rfirst; r < RR; r += GRID_REVIEW) {
        const int rn = r + GRID_REVIEW;
        const int rc = (rn < RR) ? rn : r;

        const float4 v4 = reinterpret_cast<float4*>(v_sh)[lane];

        // ---- per-lane partial dots for this warp's 8 s-values ----
        float p[8];
        #pragma unroll
        for (int i = 0; i < 8; ++i)
            p[i] = ev[i].x * v4.x + ev[i].y * v4.y +
                   ev[i].z * v4.z + ev[i].w * v4.w;

        // ---- prefetch next review's tokens + v (regs; consumed in tail) ----
        int tokreg_n = 0;
        if (lane < 8) tokreg_n = __ldg(tok + rc * SS + w * 8 + lane);
        float v_pf_n = (t < DD) ? g_v[(size_t)rc * DD + t] : 0.f;

        // ---- folding multi-reduce: 8 dots -> 9 shfls ----
        float q[4];
        #pragma unroll
        for (int i = 0; i < 4; ++i) {
            float send = (lane & 16) ? p[i] : p[i + 4];
            float keep = (lane & 16) ? p[i + 4] : p[i];
            q[i] = keep + __shfl_xor_sync(0xffffffffu, send, 16);
        }
        float u[2];
        #pragma unroll
        for (int i = 0; i < 2; ++i) {
            float send = (lane & 8) ? q[i] : q[i + 2];
            float keep = (lane & 8) ? q[i + 2] : q[i];
            u[i] = keep + __shfl_xor_sync(0xffffffffu, send, 8);
        }
        float dx;
        {
            float send = (lane & 4) ? u[0] : u[1];
            float keep = (lane & 4) ? u[1] : u[0];
            dx = keep + __shfl_xor_sync(0xffffffffu, send, 4);
        }
        dx += __shfl_xor_sync(0xffffffffu, dx, 2);
        dx += __shfl_xor_sync(0xffffffffu, dx, 1);
        if ((lane & 3) == 0) ax_sh[w * 8 + ((lane >> 2) & 7)] = dx;
        __syncthreads();                                   // B1

        // ---- softmax over S=64 (redundant in every warp) + z partial ----
        float4 z = make_float4(0.f, 0.f, 0.f, 0.f);
        {
            float a = ax_sh[lane];
            float b = ax_sh[lane + 32];
            float m = fmaxf(a, b);
            #pragma unroll
            for (int o = 16; o; o >>= 1) m = fmaxf(m, __shfl_xor_sync(0xffffffffu, m, o));
            float ea = __expf(a - m), eb = __expf(b - m);
            float s = ea + eb;
            #pragma unroll
            for (int o = 16; o; o >>= 1) s += __shfl_xor_sync(0xffffffffu, s, o);
            float inv = __fdividef(1.f, s);
            float sel  = (w & 4) ? eb : ea;
            int   base = (w & 3) * 8;
            #pragma unroll
            for (int i = 0; i < 8; ++i) {
                float av = __shfl_sync(0xffffffffu, sel, base + i) * inv;
                z.x = fmaf(av, ev[i].x, z.x);
                z.y = fmaf(av, ev[i].y, z.y);
                z.z = fmaf(av, ev[i].z, z.z);
                z.w = fmaf(av, ev[i].w, z.w);
            }
        }

        // ---- ev[] now dead: ISSUE NEXT REVIEW'S GATHERS (latency hides
        //      under the whole aspect tail below) ----
        #pragma unroll
        for (int i = 0; i < 8; ++i) {
            int id = __shfl_sync(0xffffffffu, tokreg_n, i);
            ev[i] = reinterpret_cast<const float4*>(wemb + (size_t)id * DD)[lane];
        }

        reinterpret_cast<float4*>(red)[w * 32 + lane] = z;
        __syncthreads();                                   // B2

        // ---- z[d]: cross-warp sum of 8 partials ----
        if (t < DD) {
            float s = 0.f;
            #pragma unroll
            for (int w2 = 0; w2 < 8; ++w2)
                s += red[w2 * DD + t];
            z_sh[t] = s;
        }
        __syncthreads();                                   // B3

        // ---- aspect logits: thread (part, lane=k), float4 loads ----
        {
            float a = 0.f;
            const float4* zp4 =
                reinterpret_cast<const float4*>(z_sh + part * 16);
            #pragma unroll
            for (int j4 = 0; j4 < 4; ++j4) {
                float4 zv = zp4[j4];        // broadcast, 1 wf
                float4 wv = wwrow4[j4];     // conflict-free LDS.128
                a = fmaf(zv.x, wv.x, a);
                a = fmaf(zv.y, wv.y, a);
                a = fmaf(zv.z, wv.z, a);
                a = fmaf(zv.w, wv.w, a);
            }
            lpart[part * KK + lane] = a;
        }
        __syncthreads();                                   // B4

        // ---- K-softmax: warp 0 only -> p_sh ----
        if (w == 0) {
            float a = wb_sh[lane];
            #pragma unroll
            for (int pp = 0; pp < 8; ++pp) a += lpart[pp * KK + lane];
            float m = a;
            #pragma unroll
            for (int o = 16; o; o >>= 1) m = fmaxf(m, __shfl_xor_sync(0xffffffffu, m, o));
            float e = __expf(a - m);
            float s = e;
            #pragma unroll
            for (int o = 16; o; o >>= 1) s += __shfl_xor_sync(0xffffffffu, s, o);
            p_sh[lane] = e * __fdividef(1.f, s);
        }
        __syncthreads();                                   // B5

        // ---- r_s[d] = Tb[d] + sum_k p[k] * Tw[k][d] (p via float4 bcast) ----
        if (t < DD) {
            float a = tb_reg;
            const float4* pp4 = reinterpret_cast<const float4*>(p_sh);
            #pragma unroll
            for (int k4 = 0; k4 < 8; ++k4) {
                float4 pv = pp4[k4];        // broadcast, 1 wf (was 4)
                a = fmaf(pv.x, twS[(k4 * 4 + 0) * DD + t], a);
                a = fmaf(pv.y, twS[(k4 * 4 + 1) * DD + t], a);
                a = fmaf(pv.z, twS[(k4 * 4 + 2) * DD + t], a);
                a = fmaf(pv.w, twS[(k4 * 4 + 3) * DD + t], a);
            }
            g_rs[(size_t)r * DD + t] = a;
        }

        // ---- stage next v into SMEM; rotate token regs ----
        if (t < DD) v_sh[t] = v_pf_n;
        tokreg = tokreg_n;
        __syncthreads();   // B6: protects ax_sh/red/lpart/p_sh/v_sh for next iter
    }
}

// ================= kernel 3: fused segment-mean + prediction =================
__global__ void __launch_bounds__(256) final_kernel(
    const int*   __restrict__ user, const int* __restrict__ item,
    const int*   __restrict__ uidx, const int* __restrict__ iidx,
    const float* __restrict__ uemb, const float* __restrict__ iemb,
    const float* __restrict__ avg,  float* __restrict__ out)
{
    __shared__ float sh[256];
    __shared__ float red[4];

    const int b    = blockIdx.x;
    const int t    = threadIdx.x;
    const int side = t >> 7;          // 0 = user, 1 = item
    const int d    = t & 127;

    float uf = 0.f, itf = 0.f;
    if (t < DD) {
        uf  = uemb[(size_t)user[b] * DD + t];
        itf = iemb[(size_t)item[b] * DD + t];
    }

    const int* idxp = side ? iidx : uidx;
    const int  base = b * PER;

    int ids[PER];
    #pragma unroll
    for (int j = 0; j < PER; ++j)
        ids[j] = __ldg(idxp + base + j);      // PER independent LDG

    float sum = 0.f;
    #pragma unroll
    for (int j = 0; j < PER; ++j)
        sum += g_rs[(size_t)ids[j] * DD + d]; // PER independent LDG

    sh[t] = sum * (1.0f / (float)PER);
    __syncthreads();

    if (t < DD) {
        float p = sh[t] * sh[t + 128] + uf * itf;
        #pragma unroll
        for (int o = 16; o; o >>= 1) p += __shfl_xor_sync(0xffffffffu, p, o);
        if ((t & 31) == 0) red[t >> 5] = p;
    }
    __syncthreads();
    if (t == 0) out[b] = red[0] + red[1] + red[2] + red[3] + avg[0];
}

// ---------------- launch ----------------
extern "C" void kernel_launch(void* const* d_in, const int* in_sizes, int n_in,
                              void* d_out, int out_size)
{
    const int*   user = (const int*)  d_in[0];
    const int*   item = (const int*)  d_in[1];
    const int*   hrev = (const int*)  d_in[2];
    const float* ypos = (const float*)d_in[3];
    const int*   uidx = (const int*)  d_in[4];
    const int*   iidx = (const int*)  d_in[6];
    const float* wemb = (const float*)d_in[8];
    const float* Mw   = (const float*)d_in[9];
    // d_in[10] = M_b: constant shift over s -> cancels in softmax, unused
    const float* Ww   = (const float*)d_in[11];
    const float* Wb   = (const float*)d_in[12];
    const float* Tw   = (const float*)d_in[13];
    const float* Tb   = (const float*)d_in[14];
    const float* uemb = (const float*)d_in[15];
    const float* iemb = (const float*)d_in[16];
    const float* avg  = (const float*)d_in[17];
    float* out = (float*)d_out;

    vprep_kernel <<<RR / 32, 128>>>(Mw, ypos);   // 625 blocks x 32 reviews, 1 wave
    review_kernel<<<GRID_REVIEW, 256>>>(hrev, wemb, Ww, Wb, Tw, Tb);
    final_kernel <<<BB, 256>>>(user, item, uidx, iidx, uemb, iemb, avg, out);
}